// round 1
// baseline (speedup 1.0000x reference)
#include <cuda_runtime.h>
#include <math.h>

// GridSelfAttention: N=384, C=128, H=4, D=32
// Stage 1: LN + bias + {q,k,v,gate} projections
// Stage 2: per-(b,h) attention with fused masked softmax
// Stage 3: (wa * gate) @ w_out^T

#define NSEQ 384
#define CDIM 128
#define NHEAD 4
#define DHEAD 32
#define NTOK (NSEQ * NSEQ)          // 147456 rows
#define NNMAT (NSEQ * NSEQ)

// ---- scratch (device globals; no allocation allowed) ----
__device__ float g_q[NSEQ * NHEAD * NSEQ * DHEAD];    // [b,h,n,d]
__device__ float g_k[NSEQ * NHEAD * NSEQ * DHEAD];
__device__ float g_v[NSEQ * NHEAD * NSEQ * DHEAD];
__device__ float g_gate[NTOK * CDIM];                 // sigmoid(x @ Wg^T)
__device__ float g_bias[NHEAD * NNMAT];               // [h,i,j]
__device__ float g_wa[NTOK * CDIM];                   // attention output [b,n,c]

// shared tile geometry
#define MT 64            // rows per block (stage 1/3)
#define XPAD 132         // padded row stride for 128-wide tiles
#define KVPAD 36         // padded row stride for 32-wide q/k/v rows
#define SPAD 388         // padded row stride for 384-wide logit rows

// =====================================================================
// Kernel 1: LayerNorm + bias + q/k/v/gate projections
// block: 256 threads, tile 64 rows x 128 cols
// =====================================================================
__global__ void k_proj(const float* __restrict__ pair,
                       const float* __restrict__ ln_w,
                       const float* __restrict__ ln_b,
                       const float* __restrict__ w_bias,
                       const float* __restrict__ w_q,
                       const float* __restrict__ w_k,
                       const float* __restrict__ w_v,
                       const float* __restrict__ w_gate)
{
    extern __shared__ float sm[];
    float* Xs = sm;                        // [64][132]
    float* Ws = sm + MT * XPAD;            // [128][132]

    const int tid = threadIdx.x;
    const int r0  = blockIdx.x * MT;

    // ---- load pair tile (2048 float4) ----
#pragma unroll
    for (int i = 0; i < 8; ++i) {
        int f = tid + i * 256;
        int L = f * 4;
        int row = L >> 7, col = L & 127;
        float4 v = *(const float4*)(pair + (size_t)(r0 + row) * CDIM + col);
        *(float4*)(Xs + row * XPAD + col) = v;
    }
    __syncthreads();

    // ---- layernorm: 4 threads per row ----
    {
        int row = tid >> 2, l4 = tid & 3;
        float s = 0.f, s2 = 0.f;
        float* xr = Xs + row * XPAD;
#pragma unroll
        for (int c = l4 * 32; c < l4 * 32 + 32; ++c) {
            float x = xr[c]; s += x; s2 += x * x;
        }
        s  += __shfl_xor_sync(0xffffffffu, s, 1);
        s  += __shfl_xor_sync(0xffffffffu, s, 2);
        s2 += __shfl_xor_sync(0xffffffffu, s2, 1);
        s2 += __shfl_xor_sync(0xffffffffu, s2, 2);
        float mean = s * (1.f / 128.f);
        float var  = s2 * (1.f / 128.f) - mean * mean;
        float rstd = rsqrtf(var + 1e-5f);
#pragma unroll
        for (int c = l4 * 32; c < l4 * 32 + 32; ++c) {
            float x = xr[c];
            xr[c] = (x - mean) * rstd * ln_w[c] + ln_b[c];
        }
    }
    __syncthreads();

    // ---- per-head pair bias: one (row, head) dot per thread ----
    {
        int row = tid >> 2, h = tid & 3;
        const float* xr = Xs + row * XPAD;
        const float* wb = w_bias + h * CDIM;
        float s = 0.f;
#pragma unroll 8
        for (int c = 0; c < CDIM; ++c) s += xr[c] * wb[c];
        g_bias[h * NNMAT + r0 + row] = s;
    }

    // ---- GEMMs: [64x128] @ [128x128]^T for each of q,k,v,gate ----
    const float* Wp[4] = {w_q, w_k, w_v, w_gate};
    float* Qp[3] = {g_q, g_k, g_v};
    const int tx = tid & 15, ty = tid >> 4;
    int rb[4], rn[4];
#pragma unroll
    for (int i = 0; i < 4; ++i) {
        int r = r0 + ty * 4 + i;
        rb[i] = r / NSEQ;
        rn[i] = r - rb[i] * NSEQ;
    }

    for (int w = 0; w < 4; ++w) {
        __syncthreads();
        const float* W = Wp[w];
#pragma unroll
        for (int i = 0; i < 16; ++i) {
            int f = tid + i * 256;
            int L = f * 4;
            int row = L >> 7, col = L & 127;
            *(float4*)(Ws + row * XPAD + col) = *(const float4*)(W + row * CDIM + col);
        }
        __syncthreads();

        float acc[4][8];
#pragma unroll
        for (int i = 0; i < 4; ++i)
#pragma unroll
            for (int j = 0; j < 8; ++j) acc[i][j] = 0.f;

#pragma unroll 2
        for (int kk = 0; kk < CDIM; kk += 4) {
            float4 a[4], bv[8];
#pragma unroll
            for (int i = 0; i < 4; ++i)
                a[i] = *(const float4*)(Xs + (ty * 4 + i) * XPAD + kk);
#pragma unroll
            for (int j = 0; j < 8; ++j)
                bv[j] = *(const float4*)(Ws + (j * 16 + tx) * XPAD + kk);
#pragma unroll
            for (int i = 0; i < 4; ++i)
#pragma unroll
                for (int j = 0; j < 8; ++j)
                    acc[i][j] += a[i].x * bv[j].x + a[i].y * bv[j].y
                               + a[i].z * bv[j].z + a[i].w * bv[j].w;
        }

        if (w < 3) {
            float* dst = Qp[w];
#pragma unroll
            for (int i = 0; i < 4; ++i)
#pragma unroll
                for (int j = 0; j < 8; ++j) {
                    int n = j * 16 + tx;
                    dst[((size_t)(rb[i] * NHEAD + (n >> 5)) * NSEQ + rn[i]) * DHEAD + (n & 31)]
                        = acc[i][j];
                }
        } else {
#pragma unroll
            for (int i = 0; i < 4; ++i) {
                int r = r0 + ty * 4 + i;
#pragma unroll
                for (int j = 0; j < 8; ++j) {
                    int n = j * 16 + tx;
                    g_gate[(size_t)r * CDIM + n] = 1.f / (1.f + __expf(-acc[i][j]));
                }
            }
        }
    }
}

// =====================================================================
// Kernel 2: attention for one (b,h) x 64-query tile
// grid: (6, 1536), block 256 threads
// smem: Qs[64][36] Ks[384][36] Vs[384][36] S[64][388]  (~219 KB)
// =====================================================================
__global__ void k_attn(const int* __restrict__ mask)
{
    extern __shared__ float sm[];
    float* Qs = sm;                              // 64*36
    float* Ks = Qs + 64 * KVPAD;                 // 384*36
    float* Vs = Ks + NSEQ * KVPAD;               // 384*36
    float* S  = Vs + NSEQ * KVPAD;               // 64*388

    const int tid = threadIdx.x;
    const int bh = blockIdx.y;
    const int bb = bh >> 2, h = bh & 3;
    const int q0 = blockIdx.x * 64;
    const size_t base = (size_t)bh * NSEQ * DHEAD;
    const float scale = 0.17677669529663687f;    // 1/sqrt(32)

    // ---- load Q tile (scaled) ----
#pragma unroll
    for (int i = 0; i < 2; ++i) {
        int f = tid + i * 256;                   // 512 float4
        int row = f >> 3, c4 = (f & 7) * 4;
        float4 v = *(const float4*)(g_q + base + (size_t)(q0 + row) * DHEAD + c4);
        v.x *= scale; v.y *= scale; v.z *= scale; v.w *= scale;
        *(float4*)(Qs + row * KVPAD + c4) = v;
    }
    // ---- load K and V (full 384 keys) ----
#pragma unroll
    for (int i = 0; i < 12; ++i) {
        int f = tid + i * 256;                   // 3072 float4
        int row = f >> 3, c4 = (f & 7) * 4;
        *(float4*)(Ks + row * KVPAD + c4) =
            *(const float4*)(g_k + base + (size_t)row * DHEAD + c4);
        *(float4*)(Vs + row * KVPAD + c4) =
            *(const float4*)(g_v + base + (size_t)row * DHEAD + c4);
    }
    __syncthreads();

    // ---- S = Q K^T : 3 chunks of 128 keys, 4x8 micro-tiles ----
    {
        const int tx = tid & 15, ty = tid >> 4;
        for (int kc = 0; kc < 3; ++kc) {
            float acc[4][8];
#pragma unroll
            for (int i = 0; i < 4; ++i)
#pragma unroll
                for (int j = 0; j < 8; ++j) acc[i][j] = 0.f;

#pragma unroll
            for (int kk = 0; kk < DHEAD; kk += 4) {
                float4 a[4], bv[8];
#pragma unroll
                for (int i = 0; i < 4; ++i)
                    a[i] = *(const float4*)(Qs + (ty * 4 + i) * KVPAD + kk);
#pragma unroll
                for (int j = 0; j < 8; ++j)
                    bv[j] = *(const float4*)(Ks + (kc * 128 + j * 16 + tx) * KVPAD + kk);
#pragma unroll
                for (int i = 0; i < 4; ++i)
#pragma unroll
                    for (int j = 0; j < 8; ++j)
                        acc[i][j] += a[i].x * bv[j].x + a[i].y * bv[j].y
                                   + a[i].z * bv[j].z + a[i].w * bv[j].w;
            }
#pragma unroll
            for (int i = 0; i < 4; ++i)
#pragma unroll
                for (int j = 0; j < 8; ++j)
                    S[(ty * 4 + i) * SPAD + kc * 128 + j * 16 + tx] = acc[i][j];
        }
    }
    __syncthreads();

    // ---- masked softmax over 384 keys (4 threads per query row) ----
    {
        int row = tid >> 2, l4 = tid & 3;
        const float* brow = g_bias + (size_t)h * NNMAT + (size_t)(q0 + row) * NSEQ;
        const int* mrow = mask + bb * NSEQ;
        float* Srow = S + row * SPAD;
        float mx = -3.0e38f;
#pragma unroll 4
        for (int k2 = l4 * 96; k2 < l4 * 96 + 96; ++k2) {
            float l = Srow[k2] + brow[k2];
            if (mrow[k2] == 0) l = -1e9f;
            Srow[k2] = l;
            mx = fmaxf(mx, l);
        }
        mx = fmaxf(mx, __shfl_xor_sync(0xffffffffu, mx, 1));
        mx = fmaxf(mx, __shfl_xor_sync(0xffffffffu, mx, 2));
        float s = 0.f;
#pragma unroll 4
        for (int k2 = l4 * 96; k2 < l4 * 96 + 96; ++k2) {
            float e = __expf(Srow[k2] - mx);
            Srow[k2] = e;
            s += e;
        }
        s += __shfl_xor_sync(0xffffffffu, s, 1);
        s += __shfl_xor_sync(0xffffffffu, s, 2);
        if (l4 == 0) Qs[row] = 1.f / s;          // Qs reused for inv-sums
    }
    __syncthreads();

    // ---- O = P V : [64 x 32], 2x4 micro-tiles, K=384 ----
    {
        int txd = tid & 7, tyq = tid >> 3;       // d0 = txd*4, rows m0 = tyq*2
        int m0 = tyq * 2, d0 = txd * 4;
        float acc[2][4];
#pragma unroll
        for (int i = 0; i < 2; ++i)
#pragma unroll
            for (int j = 0; j < 4; ++j) acc[i][j] = 0.f;

#pragma unroll 2
        for (int k = 0; k < NSEQ; k += 4) {
            float4 a0 = *(const float4*)(S + m0 * SPAD + k);
            float4 a1 = *(const float4*)(S + (m0 + 1) * SPAD + k);
            float4 b0 = *(const float4*)(Vs + (k + 0) * KVPAD + d0);
            float4 b1 = *(const float4*)(Vs + (k + 1) * KVPAD + d0);
            float4 b2 = *(const float4*)(Vs + (k + 2) * KVPAD + d0);
            float4 b3 = *(const float4*)(Vs + (k + 3) * KVPAD + d0);
            acc[0][0] += a0.x * b0.x + a0.y * b1.x + a0.z * b2.x + a0.w * b3.x;
            acc[0][1] += a0.x * b0.y + a0.y * b1.y + a0.z * b2.y + a0.w * b3.y;
            acc[0][2] += a0.x * b0.z + a0.y * b1.z + a0.z * b2.z + a0.w * b3.z;
            acc[0][3] += a0.x * b0.w + a0.y * b1.w + a0.z * b2.w + a0.w * b3.w;
            acc[1][0] += a1.x * b0.x + a1.y * b1.x + a1.z * b2.x + a1.w * b3.x;
            acc[1][1] += a1.x * b0.y + a1.y * b1.y + a1.z * b2.y + a1.w * b3.y;
            acc[1][2] += a1.x * b0.z + a1.y * b1.z + a1.z * b2.z + a1.w * b3.z;
            acc[1][3] += a1.x * b0.w + a1.y * b1.w + a1.z * b2.w + a1.w * b3.w;
        }
        float inv0 = Qs[m0], inv1 = Qs[m0 + 1];
#pragma unroll
        for (int j = 0; j < 4; ++j) {
            g_wa[(size_t)(bb * NSEQ + q0 + m0) * CDIM + h * DHEAD + d0 + j] = acc[0][j] * inv0;
            g_wa[(size_t)(bb * NSEQ + q0 + m0 + 1) * CDIM + h * DHEAD + d0 + j] = acc[1][j] * inv1;
        }
    }
}

// =====================================================================
// Kernel 3: out = (wa * gate) @ w_out^T
// =====================================================================
__global__ void k_out(const float* __restrict__ w_out, float* __restrict__ out)
{
    extern __shared__ float sm[];
    float* Xs = sm;
    float* Ws = sm + MT * XPAD;

    const int tid = threadIdx.x;
    const int r0  = blockIdx.x * MT;

#pragma unroll
    for (int i = 0; i < 8; ++i) {
        int f = tid + i * 256;
        int L = f * 4;
        int row = L >> 7, col = L & 127;
        float4 a = *(const float4*)(g_wa + (size_t)(r0 + row) * CDIM + col);
        float4 g = *(const float4*)(g_gate + (size_t)(r0 + row) * CDIM + col);
        a.x *= g.x; a.y *= g.y; a.z *= g.z; a.w *= g.w;
        *(float4*)(Xs + row * XPAD + col) = a;
    }
#pragma unroll
    for (int i = 0; i < 16; ++i) {
        int f = tid + i * 256;
        int L = f * 4;
        int row = L >> 7, col = L & 127;
        *(float4*)(Ws + row * XPAD + col) = *(const float4*)(w_out + row * CDIM + col);
    }
    __syncthreads();

    const int tx = tid & 15, ty = tid >> 4;
    float acc[4][8];
#pragma unroll
    for (int i = 0; i < 4; ++i)
#pragma unroll
        for (int j = 0; j < 8; ++j) acc[i][j] = 0.f;

#pragma unroll 2
    for (int kk = 0; kk < CDIM; kk += 4) {
        float4 a[4], bv[8];
#pragma unroll
        for (int i = 0; i < 4; ++i)
            a[i] = *(const float4*)(Xs + (ty * 4 + i) * XPAD + kk);
#pragma unroll
        for (int j = 0; j < 8; ++j)
            bv[j] = *(const float4*)(Ws + (j * 16 + tx) * XPAD + kk);
#pragma unroll
        for (int i = 0; i < 4; ++i)
#pragma unroll
            for (int j = 0; j < 8; ++j)
                acc[i][j] += a[i].x * bv[j].x + a[i].y * bv[j].y
                           + a[i].z * bv[j].z + a[i].w * bv[j].w;
    }

#pragma unroll
    for (int i = 0; i < 4; ++i) {
        int r = r0 + ty * 4 + i;
#pragma unroll
        for (int j = 0; j < 8; ++j) {
            int n = j * 16 + tx;
            out[(size_t)r * CDIM + n] = acc[i][j];
        }
    }
}

// =====================================================================
extern "C" void kernel_launch(void* const* d_in, const int* in_sizes, int n_in,
                              void* d_out, int out_size)
{
    const float* pair   = (const float*)d_in[0];
    const int*   mask   = (const int*)  d_in[1];
    const float* ln_w   = (const float*)d_in[2];
    const float* ln_b   = (const float*)d_in[3];
    const float* w_bias = (const float*)d_in[4];
    const float* w_q    = (const float*)d_in[5];
    const float* w_k    = (const float*)d_in[6];
    const float* w_v    = (const float*)d_in[7];
    const float* w_gate = (const float*)d_in[8];
    const float* w_out  = (const float*)d_in[9];
    float* out = (float*)d_out;

    const int smem1 = (MT * XPAD + CDIM * XPAD) * (int)sizeof(float);            // ~101 KB
    const int smem2 = (64 * KVPAD + 2 * NSEQ * KVPAD + 64 * SPAD) * (int)sizeof(float); // ~219 KB

    cudaFuncSetAttribute(k_proj, cudaFuncAttributeMaxDynamicSharedMemorySize, smem1);
    cudaFuncSetAttribute(k_attn, cudaFuncAttributeMaxDynamicSharedMemorySize, smem2);
    cudaFuncSetAttribute(k_out,  cudaFuncAttributeMaxDynamicSharedMemorySize, smem1);

    k_proj<<<NTOK / MT, 256, smem1>>>(pair, ln_w, ln_b, w_bias, w_q, w_k, w_v, w_gate);

    dim3 g2(NSEQ / 64, NSEQ * NHEAD);   // (6, 1536)
    k_attn<<<g2, 256, smem2>>>(mask);

    k_out<<<NTOK / MT, 256, smem1>>>(w_out, out);
}

// round 5
// speedup vs baseline: 1.6039x; 1.6039x over previous
#include <cuda_runtime.h>
#include <math.h>

// GridSelfAttention: N=384, C=128, H=4, D=32
// fp32 throughout, packed f32x2 FMA (fma.rn.f32x2 -> FFMA2) in every GEMM inner loop.

#define NSEQ 384
#define CDIM 128
#define NHEAD 4
#define DHEAD 32
#define NTOK (NSEQ * NSEQ)
#define NNMAT (NSEQ * NSEQ)

typedef unsigned long long u64;
typedef ulonglong2 u64x2;

__device__ __forceinline__ void fma2(u64 &d, u64 a, u64 b) {
    asm("fma.rn.f32x2 %0, %1, %2, %0;" : "+l"(d) : "l"(a), "l"(b));
}
__device__ __forceinline__ float hsum2(u64 v) {
    float x, y;
    asm("mov.b64 {%0,%1}, %2;" : "=f"(x), "=f"(y) : "l"(v));
    return x + y;
}

// ---- scratch (device globals; no allocation allowed) ----
__device__ float g_q[NSEQ * NHEAD * NSEQ * DHEAD];    // [b,h,n,d]
__device__ float g_k[NSEQ * NHEAD * NSEQ * DHEAD];
__device__ float g_v[NSEQ * NHEAD * NSEQ * DHEAD];
__device__ float g_gate[NTOK * CDIM];
__device__ float g_bias[NHEAD * NNMAT];               // [h, i*N+j]
__device__ float g_wa[NTOK * CDIM];

#define MT1 128
#define XPAD 132
#define KPAD 36
#define VTP 388
#define SPD 416

// =====================================================================
// Kernel 1: LN + per-head bias + q/k/v/gate projections
// tile 128x128, 256 threads, 8x8 micro-tiles, k-packed f32x2
// =====================================================================
__global__ __launch_bounds__(256, 1)
void k_proj(const float* __restrict__ pair,
            const float* __restrict__ ln_w,
            const float* __restrict__ ln_b,
            const float* __restrict__ w_bias,
            const float* __restrict__ w_q,
            const float* __restrict__ w_k,
            const float* __restrict__ w_v,
            const float* __restrict__ w_gate)
{
    extern __shared__ float sm[];
    float* Xs = sm;                    // [128][132]
    float* Ws = sm + MT1 * XPAD;       // [128][132]

    const int tid = threadIdx.x;
    const int r0  = blockIdx.x * MT1;

    // load pair tile (4096 float4)
#pragma unroll
    for (int i = 0; i < 16; ++i) {
        int f = tid + i * 256;
        int row = f >> 5, c4 = (f & 31) * 4;
        *(float4*)(Xs + row * XPAD + c4) =
            *(const float4*)(pair + (size_t)(r0 + row) * CDIM + c4);
    }
    __syncthreads();

    // layernorm: 2 threads per row
    {
        int row = tid >> 1, half = tid & 1;
        float* xr = Xs + row * XPAD;
        float s = 0.f, s2 = 0.f;
#pragma unroll 8
        for (int c = half * 64; c < half * 64 + 64; ++c) {
            float x = xr[c]; s += x; s2 += x * x;
        }
        s  += __shfl_xor_sync(0xffffffffu, s, 1);
        s2 += __shfl_xor_sync(0xffffffffu, s2, 1);
        float mean = s * (1.f / 128.f);
        float var  = s2 * (1.f / 128.f) - mean * mean;
        float rstd = rsqrtf(var + 1e-5f);
#pragma unroll 8
        for (int c = half * 64; c < half * 64 + 64; ++c)
            xr[c] = (xr[c] - mean) * rstd * ln_w[c] + ln_b[c];
    }
    __syncthreads();

    // per-head pair bias: 2 heads per thread
    {
        int row = tid >> 1, hp = tid & 1;
        const float* xr = Xs + row * XPAD;
#pragma unroll
        for (int hh = 0; hh < 2; ++hh) {
            int h = hp * 2 + hh;
            const float* wb = w_bias + h * CDIM;
            float s = 0.f;
#pragma unroll 8
            for (int c = 0; c < CDIM; ++c) s += xr[c] * wb[c];
            g_bias[(size_t)h * NNMAT + r0 + row] = s;
        }
    }

    // 4 GEMMs: X[128x128] @ W^T[128x128]
    const float* Wp[4] = {w_q, w_k, w_v, w_gate};
    const int tx = tid & 15, ty = tid >> 4;

    for (int w = 0; w < 4; ++w) {
        __syncthreads();
        const float* W = Wp[w];
#pragma unroll
        for (int i = 0; i < 16; ++i) {
            int f = tid + i * 256;
            int row = f >> 5, c4 = (f & 31) * 4;
            *(float4*)(Ws + row * XPAD + c4) = *(const float4*)(W + row * CDIM + c4);
        }
        __syncthreads();

        u64 acc[8][8];
#pragma unroll
        for (int i = 0; i < 8; ++i)
#pragma unroll
            for (int j = 0; j < 8; ++j) acc[i][j] = 0ull;

#pragma unroll 2
        for (int kk = 0; kk < CDIM; kk += 4) {
            u64x2 a[8];
#pragma unroll
            for (int i = 0; i < 8; ++i)
                a[i] = *(const u64x2*)(Xs + (i * 16 + ty) * XPAD + kk);
#pragma unroll
            for (int j = 0; j < 8; ++j) {
                u64x2 b = *(const u64x2*)(Ws + (j * 16 + tx) * XPAD + kk);
#pragma unroll
                for (int i = 0; i < 8; ++i) {
                    fma2(acc[i][j], a[i].x, b.x);
                    fma2(acc[i][j], a[i].y, b.y);
                }
            }
        }

        if (w < 3) {
            float* dst = (w == 0) ? g_q : (w == 1) ? g_k : g_v;
#pragma unroll
            for (int i = 0; i < 8; ++i) {
                int r  = r0 + i * 16 + ty;
                int b_ = r / NSEQ;
                int nr = r - b_ * NSEQ;
#pragma unroll
                for (int j = 0; j < 8; ++j) {
                    int n = j * 16 + tx;
                    dst[((size_t)(b_ * NHEAD + (n >> 5)) * NSEQ + nr) * DHEAD + (n & 31)]
                        = hsum2(acc[i][j]);
                }
            }
        } else {
#pragma unroll
            for (int i = 0; i < 8; ++i) {
                int r = r0 + i * 16 + ty;
#pragma unroll
                for (int j = 0; j < 8; ++j) {
                    int n = j * 16 + tx;
                    float v = hsum2(acc[i][j]);
                    g_gate[(size_t)r * CDIM + n] = 1.f / (1.f + __expf(-v));
                }
            }
        }
    }
}

// =====================================================================
// Kernel 2: attention, one (b,h) per block, loops 6 q-tiles of 64.
// 256 threads. K rows pad-36; V transposed (k-contiguous, pad-388);
// S rows pad-416 with (m&7)*4 skew for conflict-free strided PV loads.
// =====================================================================
__global__ __launch_bounds__(256, 1)
void k_attn(const int* __restrict__ mask)
{
    extern __shared__ float sm[];
    float* Ks = sm;                         // 384*36
    float* Vt = Ks + NSEQ * KPAD;           // 32*388
    float* S  = Vt + DHEAD * VTP;           // 64*416
    float* Qs = S  + 64 * SPD;              // 64*36
    float* inv = Qs + 64 * KPAD;            // 64
    int*   Ms = (int*)(inv + 64);           // 384

    const int tid = threadIdx.x;
    const int bh = blockIdx.x;
    const int bb = bh >> 2, h = bh & 3;
    const size_t base = (size_t)bh * NSEQ * DHEAD;
    const float scale = 0.17677669529663687f;   // 1/sqrt(32)

    // fill Ks (3072 float4, coalesced reads, pad-36 rows)
#pragma unroll
    for (int i = 0; i < 12; ++i) {
        int f = tid + i * 256;
        int n = f >> 3, c4 = (f & 7) * 4;
        *(float4*)(Ks + n * KPAD + c4) =
            *(const float4*)(g_k + base + (size_t)n * DHEAD + c4);
    }
    // fill Vt transposed: Vt[d][n], n contiguous
#pragma unroll
    for (int i = 0; i < 12; ++i) {
        int f = tid + i * 256;
        int n = f >> 3, g = f & 7;
        float4 v = *(const float4*)(g_v + base + (size_t)n * DHEAD + g * 4);
        Vt[(g * 4 + 0) * VTP + n] = v.x;
        Vt[(g * 4 + 1) * VTP + n] = v.y;
        Vt[(g * 4 + 2) * VTP + n] = v.z;
        Vt[(g * 4 + 3) * VTP + n] = v.w;
    }
    for (int f = tid; f < NSEQ; f += 256) Ms[f] = mask[bb * NSEQ + f];
    __syncthreads();

    const float* bias_h = g_bias + (size_t)h * NNMAT;

    for (int qt = 0; qt < 6; ++qt) {
        const int q0 = qt * 64;

        // load Q tile, pre-scaled
#pragma unroll
        for (int i = 0; i < 2; ++i) {
            int f = tid + i * 256;
            int n = f >> 3, c4 = (f & 7) * 4;
            float4 v = *(const float4*)(g_q + base + (size_t)(q0 + n) * DHEAD + c4);
            v.x *= scale; v.y *= scale; v.z *= scale; v.w *= scale;
            *(float4*)(Qs + n * KPAD + c4) = v;
        }
        __syncthreads();

        // ---- QK^T: 2 chunks of 192 keys, 8x6 micro-tiles, bias+mask fused ----
        {
            const int tx = tid & 31, ty = tid >> 5;
#pragma unroll
            for (int kc = 0; kc < 2; ++kc) {
                u64 acc[8][6];
#pragma unroll
                for (int i = 0; i < 8; ++i)
#pragma unroll
                    for (int j = 0; j < 6; ++j) acc[i][j] = 0ull;

#pragma unroll
                for (int kk = 0; kk < DHEAD; kk += 4) {
                    u64x2 a[8];
#pragma unroll
                    for (int i = 0; i < 8; ++i)
                        a[i] = *(const u64x2*)(Qs + (ty * 8 + i) * KPAD + kk);
#pragma unroll
                    for (int j = 0; j < 6; ++j) {
                        u64x2 b = *(const u64x2*)(Ks + (kc * 192 + j * 32 + tx) * KPAD + kk);
#pragma unroll
                        for (int i = 0; i < 8; ++i) {
                            fma2(acc[i][j], a[i].x, b.x);
                            fma2(acc[i][j], a[i].y, b.y);
                        }
                    }
                }
#pragma unroll
                for (int j = 0; j < 6; ++j) {
                    int key = kc * 192 + j * 32 + tx;
                    int km = Ms[key];
                    const float* bp = bias_h + (size_t)(q0 + ty * 8) * NSEQ + key;
#pragma unroll
                    for (int i = 0; i < 8; ++i) {
                        int m = ty * 8 + i;
                        float l = hsum2(acc[i][j]) + bp[(size_t)i * NSEQ];
                        if (km == 0) l = -1e9f;
                        S[m * SPD + i * 4 + key] = l;   // skew = (m&7)*4 = i*4
                    }
                }
            }
        }
        __syncthreads();

        // ---- masked softmax: 4 threads per row ----
        {
            int row = tid >> 2, l4 = tid & 3;
            float* Sr = S + row * SPD + (row & 7) * 4;
            float mx = -3.0e38f;
#pragma unroll 4
            for (int k2 = l4 * 96; k2 < l4 * 96 + 96; ++k2)
                mx = fmaxf(mx, Sr[k2]);
            mx = fmaxf(mx, __shfl_xor_sync(0xffffffffu, mx, 1));
            mx = fmaxf(mx, __shfl_xor_sync(0xffffffffu, mx, 2));
            float s = 0.f;
#pragma unroll 4
            for (int k2 = l4 * 96; k2 < l4 * 96 + 96; ++k2) {
                float e = __expf(Sr[k2] - mx);
                Sr[k2] = e;
                s += e;
            }
            s += __shfl_xor_sync(0xffffffffu, s, 1);
            s += __shfl_xor_sync(0xffffffffu, s, 2);
            if (l4 == 0) inv[row] = 1.f / s;
        }
        __syncthreads();

        // ---- P @ V: 4-way split-k (96 keys each), 8x4 micro-tiles ----
        {
            const int kg = tid >> 6, l64 = tid & 63;
            const int ry = l64 & 7, cx = l64 >> 3;
            u64 acc[8][4];
#pragma unroll
            for (int i = 0; i < 8; ++i)
#pragma unroll
                for (int j = 0; j < 4; ++j) acc[i][j] = 0ull;

            const int kbase = kg * 96;
#pragma unroll 2
            for (int kk = 0; kk < 96; kk += 4) {
                int k = kbase + kk;
                u64x2 a[8];
#pragma unroll
                for (int i = 0; i < 8; ++i)
                    a[i] = *(const u64x2*)(S + (i * 8 + ry) * SPD + ry * 4 + k);
#pragma unroll
                for (int j = 0; j < 4; ++j) {
                    u64x2 b = *(const u64x2*)(Vt + (j * 8 + cx) * VTP + k);
#pragma unroll
                    for (int i = 0; i < 8; ++i) {
                        fma2(acc[i][j], a[i].x, b.x);
                        fma2(acc[i][j], a[i].y, b.y);
                    }
                }
            }
            __syncthreads();   // all P reads done before scratch overwrite
#pragma unroll
            for (int i = 0; i < 8; ++i)
#pragma unroll
                for (int j = 0; j < 4; ++j)
                    S[kg * 2048 + (i * 8 + ry) * 32 + (j * 8 + cx)] = hsum2(acc[i][j]);
        }
        __syncthreads();

        // ---- reduce partials, normalize, store ----
        {
            int o0 = tid * 8;
#pragma unroll
            for (int t = 0; t < 8; ++t) {
                int o = o0 + t;
                int m = o >> 5, d = o & 31;
                float v = S[o] + S[2048 + o] + S[4096 + o] + S[6144 + o];
                v *= inv[m];
                g_wa[(size_t)(bb * NSEQ + q0 + m) * CDIM + h * DHEAD + d] = v;
            }
        }
        __syncthreads();   // before next tile reuses Qs/S
    }
}

// =====================================================================
// Kernel 3: out = (wa * gate) @ w_out^T — tile 128x128, 8x8 packed
// =====================================================================
__global__ __launch_bounds__(256, 1)
void k_out(const float* __restrict__ w_out, float* __restrict__ out)
{
    extern __shared__ float sm[];
    float* Xs = sm;
    float* Ws = sm + MT1 * XPAD;

    const int tid = threadIdx.x;
    const int r0  = blockIdx.x * MT1;

#pragma unroll
    for (int i = 0; i < 16; ++i) {
        int f = tid + i * 256;
        int row = f >> 5, c4 = (f & 31) * 4;
        float4 a = *(const float4*)(g_wa + (size_t)(r0 + row) * CDIM + c4);
        float4 g = *(const float4*)(g_gate + (size_t)(r0 + row) * CDIM + c4);
        a.x *= g.x; a.y *= g.y; a.z *= g.z; a.w *= g.w;
        *(float4*)(Xs + row * XPAD + c4) = a;
    }
#pragma unroll
    for (int i = 0; i < 16; ++i) {
        int f = tid + i * 256;
        int row = f >> 5, c4 = (f & 31) * 4;
        *(float4*)(Ws + row * XPAD + c4) = *(const float4*)(w_out + row * CDIM + c4);
    }
    __syncthreads();

    const int tx = tid & 15, ty = tid >> 4;
    u64 acc[8][8];
#pragma unroll
    for (int i = 0; i < 8; ++i)
#pragma unroll
        for (int j = 0; j < 8; ++j) acc[i][j] = 0ull;

#pragma unroll 2
    for (int kk = 0; kk < CDIM; kk += 4) {
        u64x2 a[8];
#pragma unroll
        for (int i = 0; i < 8; ++i)
            a[i] = *(const u64x2*)(Xs + (i * 16 + ty) * XPAD + kk);
#pragma unroll
        for (int j = 0; j < 8; ++j) {
            u64x2 b = *(const u64x2*)(Ws + (j * 16 + tx) * XPAD + kk);
#pragma unroll
            for (int i = 0; i < 8; ++i) {
                fma2(acc[i][j], a[i].x, b.x);
                fma2(acc[i][j], a[i].y, b.y);
            }
        }
    }

#pragma unroll
    for (int i = 0; i < 8; ++i) {
        int r = r0 + i * 16 + ty;
#pragma unroll
        for (int j = 0; j < 8; ++j) {
            int n = j * 16 + tx;
            out[(size_t)r * CDIM + n] = hsum2(acc[i][j]);
        }
    }
}

// =====================================================================
extern "C" void kernel_launch(void* const* d_in, const int* in_sizes, int n_in,
                              void* d_out, int out_size)
{
    const float* pair   = (const float*)d_in[0];
    const int*   mask   = (const int*)  d_in[1];
    const float* ln_w   = (const float*)d_in[2];
    const float* ln_b   = (const float*)d_in[3];
    const float* w_bias = (const float*)d_in[4];
    const float* w_q    = (const float*)d_in[5];
    const float* w_k    = (const float*)d_in[6];
    const float* w_v    = (const float*)d_in[7];
    const float* w_gate = (const float*)d_in[8];
    const float* w_out  = (const float*)d_in[9];
    float* out = (float*)d_out;

    const int smem1 = 2 * MT1 * XPAD * (int)sizeof(float);                    // 135168 B
    const int smem2 = (NSEQ * KPAD + DHEAD * VTP + 64 * SPD + 64 * KPAD + 64)
                        * (int)sizeof(float) + NSEQ * (int)sizeof(int);       // 222464 B

    cudaFuncSetAttribute(k_proj, cudaFuncAttributeMaxDynamicSharedMemorySize, smem1);
    cudaFuncSetAttribute(k_attn, cudaFuncAttributeMaxDynamicSharedMemorySize, smem2);
    cudaFuncSetAttribute(k_out,  cudaFuncAttributeMaxDynamicSharedMemorySize, smem1);

    k_proj<<<NTOK / MT1, 256, smem1>>>(pair, ln_w, ln_b, w_bias, w_q, w_k, w_v, w_gate);
    k_attn<<<NSEQ * NHEAD, 256, smem2>>>(mask);
    k_out<<<NTOK / MT1, 256, smem1>>>(w_out, out);
}